// round 3
// baseline (speedup 1.0000x reference)
#include <cuda_runtime.h>
#include <cstdint>

// RescaleProbMask: x (32,256,256,16) fp32
//   p[h][w] = mean over (b,c) of x[b,h,w,c]
//   out = (p>=ALPHA) ? x*ALPHA/p : 1 - beta*(1-x),  beta=(1-ALPHA)/(1-p)
// Both branches affine in x: out = scale(p)*x + offset(p).
//
// Round 3: fused single pass + cp.async double-buffered pipeline so DRAM
// loads stay in flight across the reduce/store phases (R2 showed DRAM=63%
// with phase-serialized CTAs). 32 KiB tiles, 2 buffers, 3 CTAs/SM,
// grid-stride over (h, w-tile).

#define ALPHA_C 0.25f

constexpr int B = 32, H = 256, W = 256, C = 16;
constexpr int WT = 16;                        // w per tile
constexpr int THREADS = 256;
constexpr int CHUNK_FLOATS = WT * C;          // 256 floats per b-slice
constexpr int CHUNK_F4 = CHUNK_FLOATS / 4;    // 64 float4 per b-slice (1 KiB)
constexpr int TILE_F4 = B * CHUNK_F4;         // 2048 float4 = 32 KiB
constexpr int ROW_F4 = W * C / 4;             // 1024 float4 per (b,h) row
constexpr long long BATCH_F4 = (long long)H * W * C / 4;  // 262144
constexpr int TILES = H * (W / WT);           // 4096
constexpr int F4_PER_THREAD = TILE_F4 / THREADS;  // 8

__device__ __forceinline__ void cp_async16(uint32_t smem_addr, const void* gptr) {
    asm volatile("cp.async.cg.shared.global [%0], [%1], 16;\n"
                 :: "r"(smem_addr), "l"(gptr));
}
__device__ __forceinline__ void cp_async_commit() {
    asm volatile("cp.async.commit_group;\n" ::: "memory");
}
__device__ __forceinline__ void cp_async_wait1() {
    asm volatile("cp.async.wait_group 1;\n" ::: "memory");
}

__device__ __forceinline__ void load_tile_async(uint32_t sbuf,          // smem byte addr of buffer
                                                const float4* __restrict__ x4,
                                                int tile, int tid) {
    const int h  = tile >> 4;                 // tile / (W/WT)
    const int wt = tile & 15;
    const long long base = (long long)h * ROW_F4 + (long long)wt * CHUNK_F4;
    #pragma unroll
    for (int it = 0; it < F4_PER_THREAD; ++it) {
        int f = it * THREADS + tid;
        int b = f >> 6;                       // f / 64
        int within = f & 63;
        cp_async16(sbuf + f * 16,
                   (const void*)(x4 + (long long)b * BATCH_F4 + base + within));
    }
}

__global__ __launch_bounds__(THREADS, 3)
void rescale_prob_mask_kernel(const float4* __restrict__ x4,
                              float4* __restrict__ o4) {
    extern __shared__ float4 s4[];            // 2 buffers x TILE_F4
    __shared__ float s_scale[2][WT];
    __shared__ float s_off[2][WT];

    const int tid = threadIdx.x;
    const int stride = gridDim.x;
    uint32_t sbase = (uint32_t)__cvta_generic_to_shared(s4);

    int tile = blockIdx.x;
    int buf = 0;

    // prologue: load first tile into buffer 0
    if (tile < TILES)
        load_tile_async(sbase, x4, tile, tid);
    cp_async_commit();

    for (; tile < TILES; tile += stride, buf ^= 1) {
        int next = tile + stride;
        if (next < TILES)
            load_tile_async(sbase + (buf ^ 1) * (TILE_F4 * 16), x4, next, tid);
        cp_async_commit();
        cp_async_wait1();                     // current tile's copies done
        __syncthreads();                      // visible to all threads

        const float4* t4 = s4 + buf * TILE_F4;

        // ---- reduce: 16 threads per w, each sums its c over all b ----
        {
            const float* s = reinterpret_cast<const float*>(t4);
            int wloc = tid >> 4;              // 0..15
            int c    = tid & 15;
            float acc = 0.f;
            #pragma unroll
            for (int b = 0; b < B; ++b)
                acc += s[b * CHUNK_FLOATS + wloc * C + c];
            #pragma unroll
            for (int off = 8; off > 0; off >>= 1)
                acc += __shfl_down_sync(0xFFFFFFFFu, acc, off);
            if (c == 0) {
                float p = acc * (1.0f / (float)(B * C));
                float scale, offset;
                if (p >= ALPHA_C) {
                    scale = ALPHA_C / p;
                    offset = 0.0f;
                } else {
                    float beta = (1.0f - ALPHA_C) / (1.0f - p);
                    scale = beta;
                    offset = 1.0f - beta;
                }
                s_scale[buf][wloc] = scale;
                s_off[buf][wloc]   = offset;
            }
        }
        __syncthreads();

        // ---- map + store: out = scale*x + offset ----
        const int h  = tile >> 4;
        const int wt = tile & 15;
        const long long base = (long long)h * ROW_F4 + (long long)wt * CHUNK_F4;
        #pragma unroll
        for (int it = 0; it < F4_PER_THREAD; ++it) {
            int f = it * THREADS + tid;
            int b = f >> 6;
            int within = f & 63;
            int wl = within >> 2;             // 4 float4 per w
            float sc = s_scale[buf][wl];
            float of = s_off[buf][wl];
            float4 v = t4[f];
            float4 r;
            r.x = fmaf(v.x, sc, of);
            r.y = fmaf(v.y, sc, of);
            r.z = fmaf(v.z, sc, of);
            r.w = fmaf(v.w, sc, of);
            o4[(long long)b * BATCH_F4 + base + within] = r;
        }
        __syncthreads();                      // all reads of buf done before
                                              // next iteration overwrites it
    }
}

extern "C" void kernel_launch(void* const* d_in, const int* in_sizes, int n_in,
                              void* d_out, int out_size) {
    (void)in_sizes; (void)n_in; (void)out_size;
    const float4* x4 = (const float4*)d_in[0];
    float4* o4 = (float4*)d_out;

    const int smem = 2 * TILE_F4 * sizeof(float4);   // 64 KiB dynamic
    cudaFuncSetAttribute(rescale_prob_mask_kernel,
                         cudaFuncAttributeMaxDynamicSharedMemorySize, smem);

    // 3 CTAs/SM on a 148-152 SM chip; grid-stride covers all 4096 tiles
    dim3 grid(444);
    rescale_prob_mask_kernel<<<grid, THREADS, smem>>>(x4, o4);
}

// round 5
// speedup vs baseline: 1.0907x; 1.0907x over previous
#include <cuda_runtime.h>

// RescaleProbMask: x (32,256,256,16) fp32
//   p[h][w] = mean over (b,c) of x[b,h,w,c]
//   out = (p>=ALPHA) ? x*ALPHA/p : 1 - beta*(1-x),  beta=(1-ALPHA)/(1-p)
// Affine in x: out = scale(p)*x + offset(p).
//
// Round 4: register-resident, barrier-free. One warp owns 2 w-columns.
// Lane (wl, bh, c2) holds 16 b x float2 in registers (32 regs), p is a
// shfl_xor reduce over the 16-lane (bh,c2) group. One LDG + one STG per
// element, no SMEM, no __syncthreads -> no phase serialization; DRAM
// should become the binding pipe.

#define ALPHA_C 0.25f

constexpr int B = 32, H = 256, W = 256, C = 16;
constexpr long long F2_PER_B = (long long)H * W * C / 2;   // 524288 float2
constexpr int ROW_F2 = W * C / 2;                          // 2048 float2 per h
constexpr int W_F2 = C / 2;                                // 8 float2 per w
constexpr int THREADS = 128;                               // 4 warps
// each warp covers 2 w's -> CTA covers 8 w's; blocks = 256h * 32 = 8192
constexpr int BLOCKS = H * (W / 8);

__global__ __launch_bounds__(THREADS, 5)
void rescale_prob_mask_kernel(const float2* __restrict__ x2,
                              float2* __restrict__ o2) {
    const int lane = threadIdx.x & 31;
    const int warp = threadIdx.x >> 5;
    const int gwarp = blockIdx.x * 4 + warp;   // 0..32767 (= H*W/2 w-pairs)

    const int h     = gwarp >> 7;              // 128 w-pairs per h
    const int wpair = gwarp & 127;

    const int wl = lane >> 4;                  // which w of the pair
    const int bh = (lane >> 3) & 1;            // which b-half (0: b<16, 1: b>=16)
    const int c2 = lane & 7;                   // float2 index within c

    const int w = wpair * 2 + wl;
    const long long off0 = (long long)(bh * 16) * F2_PER_B
                         + (long long)h * ROW_F2 + (long long)w * W_F2 + c2;

    const float2* __restrict__ src = x2 + off0;
    float2*       __restrict__ dst = o2 + off0;

    // ---- single global read: 16 b-steps, all independent ----
    float2 v[16];
    #pragma unroll
    for (int k = 0; k < 16; ++k)
        v[k] = __ldcs(src + (long long)k * F2_PER_B);

    // ---- reduce to p[w]: sum over this lane's 16 b x 2 c, then over the
    //      16-lane (bh,c2) group (xor bits 0..3; bit 4 = wl untouched) ----
    float acc = 0.f;
    #pragma unroll
    for (int k = 0; k < 16; ++k)
        acc += v[k].x + v[k].y;
    #pragma unroll
    for (int o = 1; o < 16; o <<= 1)
        acc += __shfl_xor_sync(0xFFFFFFFFu, acc, o);

    const float p = acc * (1.0f / (float)(B * C));
    float scale, offset;
    if (p >= ALPHA_C) {
        scale  = ALPHA_C / p;
        offset = 0.0f;
    } else {
        float beta = (1.0f - ALPHA_C) / (1.0f - p);
        scale  = beta;
        offset = 1.0f - beta;
    }

    // ---- single global write ----
    #pragma unroll
    for (int k = 0; k < 16; ++k) {
        float2 r;
        r.x = fmaf(v[k].x, scale, offset);
        r.y = fmaf(v[k].y, scale, offset);
        __stcs(dst + (long long)k * F2_PER_B, r);
    }
}

extern "C" void kernel_launch(void* const* d_in, const int* in_sizes, int n_in,
                              void* d_out, int out_size) {
    (void)in_sizes; (void)n_in; (void)out_size;
    const float2* x2 = (const float2*)d_in[0];
    float2* o2 = (float2*)d_out;
    rescale_prob_mask_kernel<<<BLOCKS, THREADS>>>(x2, o2);
}

// round 6
// speedup vs baseline: 1.0914x; 1.0007x over previous
#include <cuda_runtime.h>

// RescaleProbMask: x (32,256,256,16) fp32
//   p[h][w] = mean over (b,c) of x[b,h,w,c]
//   out = (p>=ALPHA) ? x*ALPHA/p : 1 - beta*(1-x),  beta=(1-ALPHA)/(1-p)
// Affine in x: out = scale(p)*x + offset(p).
//
// Round 6: register-resident, barrier-free (R4 structure), widened to
// float4. One warp owns a w-pair (128 contiguous bytes per b). Lane
// (wl, b4, c4) holds 8 b-steps x float4 (32 regs); p via shfl_xor over
// the 16-lane (b4,c4) group. 8 LDG.128 + 8 STG.128 per thread — half
// R4's instruction count — plus higher occupancy bound.

#define ALPHA_C 0.25f

constexpr int B = 32, H = 256, W = 256, C = 16;
constexpr long long F4_PER_B = (long long)H * W * C / 4;   // 262144 float4
constexpr int ROW_F4 = W * C / 4;                          // 1024 float4 per h
constexpr int W_F4 = C / 4;                                // 4 float4 per w
constexpr int THREADS = 128;                               // 4 warps
// one warp per w-pair: H * W/2 = 32768 warps -> 8192 CTAs
constexpr int BLOCKS = (H * (W / 2)) / (THREADS / 32);

__global__ __launch_bounds__(THREADS, 8)
void rescale_prob_mask_kernel(const float4* __restrict__ x4,
                              float4* __restrict__ o4) {
    const int lane = threadIdx.x & 31;
    const int warp = threadIdx.x >> 5;
    const int gwarp = blockIdx.x * (THREADS / 32) + warp;  // 0..32767

    const int h     = gwarp >> 7;              // 128 w-pairs per h
    const int wpair = gwarp & 127;

    const int c4 = lane & 3;                   // float4 index within c (0..3)
    const int b4 = (lane >> 2) & 3;            // b-group (8 b each)
    const int wl = lane >> 4;                  // which w of the pair

    const int w = wpair * 2 + wl;
    const long long off0 = (long long)(b4 * 8) * F4_PER_B
                         + (long long)h * ROW_F4 + (long long)w * W_F4 + c4;

    const float4* __restrict__ src = x4 + off0;
    float4*       __restrict__ dst = o4 + off0;

    // ---- single global read: 8 independent b-steps ----
    float4 v[8];
    #pragma unroll
    for (int k = 0; k < 8; ++k)
        v[k] = __ldcs(src + (long long)k * F4_PER_B);

    // ---- reduce to p[w]: lane-local 32 values, then 16-lane xor group
    //      (bits 0..3 = c4,b4; bit 4 = wl untouched) ----
    float acc = 0.f;
    #pragma unroll
    for (int k = 0; k < 8; ++k)
        acc += (v[k].x + v[k].y) + (v[k].z + v[k].w);
    #pragma unroll
    for (int o = 1; o < 16; o <<= 1)
        acc += __shfl_xor_sync(0xFFFFFFFFu, acc, o);

    const float p = acc * (1.0f / (float)(B * C));
    float scale, offset;
    if (p >= ALPHA_C) {
        scale  = ALPHA_C / p;
        offset = 0.0f;
    } else {
        float beta = (1.0f - ALPHA_C) / (1.0f - p);
        scale  = beta;
        offset = 1.0f - beta;
    }

    // ---- single global write ----
    #pragma unroll
    for (int k = 0; k < 8; ++k) {
        float4 r;
        r.x = fmaf(v[k].x, scale, offset);
        r.y = fmaf(v[k].y, scale, offset);
        r.z = fmaf(v[k].z, scale, offset);
        r.w = fmaf(v[k].w, scale, offset);
        __stcs(dst + (long long)k * F4_PER_B, r);
    }
}

extern "C" void kernel_launch(void* const* d_in, const int* in_sizes, int n_in,
                              void* d_out, int out_size) {
    (void)in_sizes; (void)n_in; (void)out_size;
    const float4* x4 = (const float4*)d_in[0];
    float4* o4 = (float4*)d_out;
    rescale_prob_mask_kernel<<<BLOCKS, THREADS>>>(x4, o4);
}